// round 1
// baseline (speedup 1.0000x reference)
#include <cuda_runtime.h>
#include <math.h>

#define NPART 32768
#define DD 32
#define PP 8
#define HH 128
#define MS 50
#define TPB 224
#define NBLK 148

__global__ __launch_bounds__(TPB, 1)
void sde_kernel(const float* __restrict__ obs,      // (8,)
                const float* __restrict__ X0,       // (N,32)
                const float* __restrict__ V0,       // (N,)
                const float* __restrict__ noise,    // (50,N,32)
                const float* __restrict__ W1,       // (42,128)
                const float* __restrict__ b1,       // (128,)
                const float* __restrict__ W2,       // (128,32)
                const float* __restrict__ b2,       // (32,)
                const float* __restrict__ theta_p,  // (1,)
                const int*   __restrict__ obsidx_p, // scalar
                const int*   __restrict__ cr_p,     // scalar
                float* __restrict__ outX,           // (N,32)
                float* __restrict__ outV)           // (N,)
{
    __shared__ float  W1T[HH][DD];   // W1T[j][i] = W1[i][j], i<32 (state part)
    __shared__ float  W2s[HH][DD];   // W2s[j][k] = W2[j][k]
    __shared__ float2 cb[HH];        // (base_j, W1[40][j]) : obs/b1/t folded + s coefficient
    __shared__ float  b2s[DD];

    const int tid = threadIdx.x;

    // ---- stage weights into shared ----
    for (int idx = tid; idx < DD * HH; idx += TPB) {
        int i = idx >> 7;            // row of W1 (feature)
        int j = idx & (HH - 1);      // column (hidden unit)
        W1T[j][i] = W1[idx];
    }
    for (int idx = tid; idx < HH * DD; idx += TPB) {
        W2s[idx >> 5][idx & 31] = W2[idx];
    }
    if (tid < DD) b2s[tid] = b2[tid];
    if (tid < HH) {
        const int j = tid;
        float base = b1[j];
        #pragma unroll
        for (int q = 0; q < PP; q++)
            base = fmaf(obs[q], W1[(DD + q) * HH + j], base);
        const float tf = (float)(*obsidx_p);
        base = fmaf(tf, W1[41 * HH + j], base);
        cb[j] = make_float2(base, W1[40 * HH + j]);
    }

    const float theta = *theta_p;
    const float crf   = (float)(*cr_p);
    const float dt    = 0.02f;            // INTERVAL / M_STEPS
    const float sqdt  = sqrtf(dt);

    const int p = tid * NBLK + (int)blockIdx.x;   // balanced particle map
    __syncthreads();
    if (p >= NPART) return;

    // ---- load particle state ----
    float X[DD], Z[DD];
    {
        const float4* xr = (const float4*)(X0 + (size_t)p * DD);
        #pragma unroll
        for (int i = 0; i < DD / 4; i++) {
            float4 v = xr[i];
            X[4*i] = v.x; X[4*i+1] = v.y; X[4*i+2] = v.z; X[4*i+3] = v.w;
        }
    }
    float V = V0[p];

    // ---- time loop (sequential dependency) ----
    for (int m = 0; m < MS; m++) {
        const float s = (float)m * dt;

        #pragma unroll
        for (int k = 0; k < DD; k++) Z[k] = b2s[k];

        #pragma unroll 2
        for (int j = 0; j < HH; j++) {
            // layer-1 pre-activation: 4 independent chains to hide FFMA latency
            float a0 = 0.f, a1 = 0.f, a2 = 0.f, a3 = 0.f;
            #pragma unroll
            for (int i = 0; i < DD; i += 4) {
                a0 = fmaf(X[i],   W1T[j][i],   a0);
                a1 = fmaf(X[i+1], W1T[j][i+1], a1);
                a2 = fmaf(X[i+2], W1T[j][i+2], a2);
                a3 = fmaf(X[i+3], W1T[j][i+3], a3);
            }
            const float2 c = cb[j];
            const float a = fmaf(s, c.y, c.x) + ((a0 + a1) + (a2 + a3));
            // tanh(a) = 1 - 2/(e^{2a}+1); ex2.approx + rcp.approx, err ~1e-6
            const float e = __expf(2.0f * a);
            const float h = 1.0f - __fdividef(2.0f, e + 1.0f);
            // layer-2 accumulate: 32 independent accumulator chains
            #pragma unroll
            for (int k = 0; k < DD; k++)
                Z[k] = fmaf(h, W2s[j][k], Z[k]);
        }

        // sum Z^2
        float sz0 = 0.f, sz1 = 0.f, sz2 = 0.f, sz3 = 0.f;
        #pragma unroll
        for (int k = 0; k < DD; k += 4) {
            sz0 = fmaf(Z[k],   Z[k],   sz0);
            sz1 = fmaf(Z[k+1], Z[k+1], sz1);
            sz2 = fmaf(Z[k+2], Z[k+2], sz2);
            sz3 = fmaf(Z[k+3], Z[k+3], sz3);
        }
        const float sumZ2 = (sz0 + sz1) + (sz2 + sz3);

        // Brownian increment + state/value update
        const float4* nrow = (const float4*)(noise + ((size_t)m * NPART + p) * DD);
        float w0 = 0.f, w1 = 0.f, w2 = 0.f, w3 = 0.f;
        #pragma unroll
        for (int i = 0; i < DD / 4; i++) {
            float4 nv = nrow[i];
            const float wx = sqdt * nv.x, wy = sqdt * nv.y,
                        wz = sqdt * nv.z, ww = sqdt * nv.w;
            w0 = fmaf(Z[4*i],   wx, w0);
            w1 = fmaf(Z[4*i+1], wy, w1);
            w2 = fmaf(Z[4*i+2], wz, w2);
            w3 = fmaf(Z[4*i+3], ww, w3);
            // X += dt*(-theta*X - cr*Z) + W
            float d0 = fmaf(-crf, Z[4*i],   -theta * X[4*i]);
            float d1 = fmaf(-crf, Z[4*i+1], -theta * X[4*i+1]);
            float d2 = fmaf(-crf, Z[4*i+2], -theta * X[4*i+2]);
            float d3 = fmaf(-crf, Z[4*i+3], -theta * X[4*i+3]);
            X[4*i]   = fmaf(dt, d0, X[4*i])   + wx;
            X[4*i+1] = fmaf(dt, d1, X[4*i+1]) + wy;
            X[4*i+2] = fmaf(dt, d2, X[4*i+2]) + wz;
            X[4*i+3] = fmaf(dt, d3, X[4*i+3]) + ww;
        }
        // V += dt*(0.5 - cr)*sumZ2 + sum(Z*W)
        V = fmaf(dt * (0.5f - crf), sumZ2, V) + ((w0 + w1) + (w2 + w3));
    }

    // ---- store ----
    float4* xo = (float4*)(outX + (size_t)p * DD);
    #pragma unroll
    for (int i = 0; i < DD / 4; i++) {
        float4 v;
        v.x = X[4*i]; v.y = X[4*i+1]; v.z = X[4*i+2]; v.w = X[4*i+3];
        xo[i] = v;
    }
    outV[p] = V;
}

extern "C" void kernel_launch(void* const* d_in, const int* in_sizes, int n_in,
                              void* d_out, int out_size) {
    const float* obs    = (const float*)d_in[0];
    const float* X0     = (const float*)d_in[1];
    const float* V0     = (const float*)d_in[2];
    const float* noise  = (const float*)d_in[3];
    const float* W1     = (const float*)d_in[4];
    const float* b1     = (const float*)d_in[5];
    const float* W2     = (const float*)d_in[6];
    const float* b2     = (const float*)d_in[7];
    const float* theta  = (const float*)d_in[8];
    const int*   obsidx = (const int*)d_in[9];
    const int*   cr     = (const int*)d_in[10];

    float* out  = (float*)d_out;
    float* outX = out;                    // (N,32) first
    float* outV = out + (size_t)NPART * DD; // then (N,)

    sde_kernel<<<NBLK, TPB>>>(obs, X0, V0, noise, W1, b1, W2, b2,
                              theta, obsidx, cr, outX, outV);
}

// round 2
// speedup vs baseline: 1.1320x; 1.1320x over previous
#include <cuda_runtime.h>
#include <math.h>

#define NPART 32768
#define DD 32
#define PP 8
#define HH 128
#define MS 50
#define TPB 224
#define NBLK 148

typedef unsigned long long u64;

// ---- packed f32x2 helpers (sm_103a; ptxas never auto-fuses these) ----
__device__ __forceinline__ u64 pack2(float lo, float hi) {
    u64 r; asm("mov.b64 %0, {%1, %2};" : "=l"(r) : "f"(lo), "f"(hi)); return r;
}
__device__ __forceinline__ void unpack2(u64 v, float& lo, float& hi) {
    asm("mov.b64 {%0, %1}, %2;" : "=f"(lo), "=f"(hi) : "l"(v));
}
__device__ __forceinline__ u64 fma2(u64 a, u64 b, u64 c) {
    u64 d; asm("fma.rn.f32x2 %0, %1, %2, %3;" : "=l"(d) : "l"(a), "l"(b), "l"(c)); return d;
}
__device__ __forceinline__ u64 add2(u64 a, u64 b) {
    u64 d; asm("add.rn.f32x2 %0, %1, %2;" : "=l"(d) : "l"(a), "l"(b)); return d;
}
__device__ __forceinline__ u64 mul2(u64 a, u64 b) {
    u64 d; asm("mul.rn.f32x2 %0, %1, %2;" : "=l"(d) : "l"(a), "l"(b)); return d;
}

__global__ __launch_bounds__(TPB, 1)
void sde_kernel(const float* __restrict__ obs,      // (8,)
                const float* __restrict__ X0,       // (N,32)
                const float* __restrict__ V0,       // (N,)
                const float* __restrict__ noise,    // (50,N,32)
                const float* __restrict__ W1,       // (42,128)
                const float* __restrict__ b1,       // (128,)
                const float* __restrict__ W2,       // (128,32)
                const float* __restrict__ b2,       // (32,)
                const float* __restrict__ theta_p,  // (1,)
                const int*   __restrict__ obsidx_p, // scalar
                const int*   __restrict__ cr_p,     // scalar
                float* __restrict__ outX,           // (N,32)
                float* __restrict__ outV)           // (N,)
{
    __shared__ __align__(16) float  W1T[HH][DD];   // W1T[j][i] = W1[i][j] (state part)
    __shared__ __align__(16) float  W2s[HH][DD];   // W2s[j][k] = W2[j][k]
    __shared__ float2 cb[HH];    // (base_j, W1[40][j]): obs/b1/t folded + s coeff
    __shared__ __align__(16) float b2s[DD];

    const int tid = threadIdx.x;

    // ---- stage weights into shared ----
    for (int idx = tid; idx < DD * HH; idx += TPB) {
        int i = idx >> 7;            // feature row of W1
        int j = idx & (HH - 1);      // hidden unit
        W1T[j][i] = W1[idx];
    }
    for (int idx = tid; idx < HH * DD; idx += TPB) {
        W2s[idx >> 5][idx & 31] = W2[idx];
    }
    if (tid < DD) b2s[tid] = b2[tid];
    if (tid < HH) {
        const int j = tid;
        float base = b1[j];
        #pragma unroll
        for (int q = 0; q < PP; q++)
            base = fmaf(obs[q], W1[(DD + q) * HH + j], base);
        base = fmaf((float)(*obsidx_p), W1[41 * HH + j], base);
        cb[j] = make_float2(base, W1[40 * HH + j]);
    }

    const float theta = *theta_p;
    const float crf   = (float)(*cr_p);
    const float dt    = 0.02f;              // INTERVAL / M_STEPS
    const float sqdt  = sqrtf(dt);

    // packed per-thread constants
    const u64 sq2  = pack2(sqdt, sqdt);
    const u64 dt2  = pack2(dt, dt);
    const u64 nth2 = pack2(-theta, -theta);
    const u64 ncr2 = pack2(-crf, -crf);
    const u64 zero2 = pack2(0.f, 0.f);

    const int p = tid * NBLK + (int)blockIdx.x;   // balanced particle map
    __syncthreads();
    if (p >= NPART) return;

    // ---- particle state, packed as 16 f32x2 pairs ----
    u64 Xp[DD / 2], Zp[DD / 2];
    {
        const ulonglong2* xr = (const ulonglong2*)(X0 + (size_t)p * DD);
        #pragma unroll
        for (int i = 0; i < DD / 4; i++) {
            ulonglong2 v = xr[i];
            Xp[2*i] = v.x; Xp[2*i+1] = v.y;
        }
    }
    float V = V0[p];

    const ulonglong2* b2p = (const ulonglong2*)b2s;

    // ---- time loop (sequential dependency) ----
    for (int m = 0; m < MS; m++) {
        const float s = (float)m * dt;

        // prefetch this step's noise row (hides DRAM latency under the MLP)
        u64 Np[DD / 2];
        {
            const ulonglong2* nrow =
                (const ulonglong2*)(noise + ((size_t)m * NPART + p) * DD);
            #pragma unroll
            for (int i = 0; i < DD / 4; i++) {
                ulonglong2 v = nrow[i];
                Np[2*i] = v.x; Np[2*i+1] = v.y;
            }
        }

        // Z := b2
        #pragma unroll
        for (int i = 0; i < DD / 8; i++) {
            ulonglong2 v = b2p[i];
            Zp[2*i] = v.x; Zp[2*i+1] = v.y;
        }
        #pragma unroll
        for (int i = DD / 4; i < DD / 2; i++) {
            // second half via the same shared row
            ulonglong2 v = b2p[i >> 1];
            Zp[i] = (i & 1) ? v.y : v.x;
        }

        #pragma unroll 2
        for (int j = 0; j < HH; j++) {
            // layer-1: 16 packed FMAs in 4 chains over 8 LDS.128
            const ulonglong2* wr = (const ulonglong2*)W1T[j];
            u64 a0 = zero2, a1 = zero2, a2 = zero2, a3 = zero2;
            #pragma unroll
            for (int i = 0; i < 4; i++) {
                ulonglong2 wa = wr[2*i];
                ulonglong2 wb = wr[2*i + 1];
                a0 = fma2(Xp[4*i],     wa.x, a0);
                a1 = fma2(Xp[4*i + 1], wa.y, a1);
                a2 = fma2(Xp[4*i + 2], wb.x, a2);
                a3 = fma2(Xp[4*i + 3], wb.y, a3);
            }
            a0 = add2(add2(a0, a1), add2(a2, a3));
            float alo, ahi; unpack2(a0, alo, ahi);
            const float2 c = cb[j];
            const float a = fmaf(s, c.y, c.x) + (alo + ahi);
            // tanh(a) = 1 - 2/(e^{2a}+1)
            const float e = __expf(2.0f * a);
            const float h = 1.0f - __fdividef(2.0f, e + 1.0f);
            const u64 h2 = pack2(h, h);
            // layer-2: 16 packed FMAs, 16 independent accumulators
            const ulonglong2* w2r = (const ulonglong2*)W2s[j];
            #pragma unroll
            for (int i = 0; i < 4; i++) {
                ulonglong2 wa = w2r[2*i];
                ulonglong2 wb = w2r[2*i + 1];
                Zp[4*i]     = fma2(h2, wa.x, Zp[4*i]);
                Zp[4*i + 1] = fma2(h2, wa.y, Zp[4*i + 1]);
                Zp[4*i + 2] = fma2(h2, wb.x, Zp[4*i + 2]);
                Zp[4*i + 3] = fma2(h2, wb.y, Zp[4*i + 3]);
            }
        }

        // sum Z^2 and Z.W, X update — all packed
        u64 s20 = zero2, s21 = zero2, s22 = zero2, s23 = zero2;
        u64 zw0 = zero2, zw1 = zero2, zw2 = zero2, zw3 = zero2;
        #pragma unroll
        for (int i = 0; i < 4; i++) {
            u64 za = Zp[4*i],     zb = Zp[4*i + 1];
            u64 zc = Zp[4*i + 2], zd = Zp[4*i + 3];
            s20 = fma2(za, za, s20);
            s21 = fma2(zb, zb, s21);
            s22 = fma2(zc, zc, s22);
            s23 = fma2(zd, zd, s23);
            u64 wa = mul2(sq2, Np[4*i]);
            u64 wb = mul2(sq2, Np[4*i + 1]);
            u64 wc = mul2(sq2, Np[4*i + 2]);
            u64 wd = mul2(sq2, Np[4*i + 3]);
            zw0 = fma2(za, wa, zw0);
            zw1 = fma2(zb, wb, zw1);
            zw2 = fma2(zc, wc, zw2);
            zw3 = fma2(zd, wd, zw3);
            // X += dt*(-theta*X - cr*Z) + W
            u64 d0 = fma2(ncr2, za, mul2(nth2, Xp[4*i]));
            u64 d1 = fma2(ncr2, zb, mul2(nth2, Xp[4*i + 1]));
            u64 d2 = fma2(ncr2, zc, mul2(nth2, Xp[4*i + 2]));
            u64 d3 = fma2(ncr2, zd, mul2(nth2, Xp[4*i + 3]));
            Xp[4*i]     = add2(fma2(dt2, d0, Xp[4*i]),     wa);
            Xp[4*i + 1] = add2(fma2(dt2, d1, Xp[4*i + 1]), wb);
            Xp[4*i + 2] = add2(fma2(dt2, d2, Xp[4*i + 2]), wc);
            Xp[4*i + 3] = add2(fma2(dt2, d3, Xp[4*i + 3]), wd);
        }
        s20 = add2(add2(s20, s21), add2(s22, s23));
        zw0 = add2(add2(zw0, zw1), add2(zw2, zw3));
        float qlo, qhi, wlo, whi;
        unpack2(s20, qlo, qhi);
        unpack2(zw0, wlo, whi);
        // V += dt*(0.5 - cr)*sumZ2 + sum(Z*W)
        V = fmaf(dt * (0.5f - crf), qlo + qhi, V) + (wlo + whi);
    }

    // ---- store ----
    ulonglong2* xo = (ulonglong2*)(outX + (size_t)p * DD);
    #pragma unroll
    for (int i = 0; i < DD / 4; i++) {
        ulonglong2 v; v.x = Xp[2*i]; v.y = Xp[2*i+1];
        xo[i] = v;
    }
    outV[p] = V;
}

extern "C" void kernel_launch(void* const* d_in, const int* in_sizes, int n_in,
                              void* d_out, int out_size) {
    const float* obs    = (const float*)d_in[0];
    const float* X0     = (const float*)d_in[1];
    const float* V0     = (const float*)d_in[2];
    const float* noise  = (const float*)d_in[3];
    const float* W1     = (const float*)d_in[4];
    const float* b1     = (const float*)d_in[5];
    const float* W2     = (const float*)d_in[6];
    const float* b2     = (const float*)d_in[7];
    const float* theta  = (const float*)d_in[8];
    const int*   obsidx = (const int*)d_in[9];
    const int*   cr     = (const int*)d_in[10];

    float* out  = (float*)d_out;
    float* outX = out;                        // (N,32) first
    float* outV = out + (size_t)NPART * DD;   // then (N,)

    sde_kernel<<<NBLK, TPB>>>(obs, X0, V0, noise, W1, b1, W2, b2,
                              theta, obsidx, cr, outX, outV);
}